// round 13
// baseline (speedup 1.0000x reference)
#include <cuda_runtime.h>
#include <cuda_fp16.h>
#include <cstdint>

// Problem constants
#define B_  32
#define N_  4096
#define E_  8192
#define D_  128
#define ROWS_TOTAL (B_*N_)        // 131072
#define NEDGE (B_*E_)             // 262144

// ---------------- device-global scratch ------------------------------------------
__device__ __half g_agg[B_*N_*D_];     // 32MB fp16 aggregation buffer
__device__ __half g_wt[2*384*128];     // transposed fp16 weights: [mat][col(384)][k(128)]

// ---------------- smem layout (bytes), 64-row CTA, 3 CTAs/SM ---------------------
// all tiles: 256B rows, XOR swizzle on 16B chunks: chunk' = chunk ^ (row&7)
#define OFF_BIAS  0                 // 768 floats (3072)
#define OFF_AG    4096              // agg  64x256B (16384)
#define OFF_AH    20480             // h    64x256B (16384)
#define OFF_B0    36864             // B ring buf 0: 64 n x 128 k (16384)
#define OFF_B1    53248             // B ring buf 1 (16384)
#define SMEM_TOTAL 69632            // x3 = 208896 <= SM smem

__device__ __forceinline__ uint32_t smem_u32(const void* p) {
    uint32_t a;
    asm("{ .reg .u64 t; cvta.to.shared.u64 t, %1; cvt.u32.u64 %0, t; }" : "=r"(a) : "l"(p));
    return a;
}
__device__ __forceinline__ void ldsm4(uint32_t d[4], uint32_t addr) {
    asm volatile("ldmatrix.sync.aligned.m8n8.x4.shared.b16 {%0,%1,%2,%3}, [%4];"
                 : "=r"(d[0]), "=r"(d[1]), "=r"(d[2]), "=r"(d[3]) : "r"(addr));
}
__device__ __forceinline__ void mma_16816(float c[4], const uint32_t a[4], uint32_t b0, uint32_t b1) {
    asm volatile(
        "mma.sync.aligned.m16n8k16.row.col.f32.f16.f16.f32 "
        "{%0,%1,%2,%3}, {%4,%5,%6,%7}, {%8,%9}, {%0,%1,%2,%3};"
        : "+f"(c[0]), "+f"(c[1]), "+f"(c[2]), "+f"(c[3])
        : "r"(a[0]), "r"(a[1]), "r"(a[2]), "r"(a[3]), "r"(b0), "r"(b1));
}
__device__ __forceinline__ float tanh_ap(float x) {
    float y; asm("tanh.approx.f32 %0, %1;" : "=f"(y) : "f"(x)); return y;
}
__device__ __forceinline__ float sigf(float x) { return fmaf(0.5f, tanh_ap(0.5f * x), 0.5f); }

#define CP_ASYNC16(dst, src) \
    asm volatile("cp.async.cg.shared.global [%0], [%1], 16;" :: "r"(dst), "l"(src) : "memory")
#define CP_COMMIT() asm volatile("cp.async.commit_group;" ::: "memory")
#define CP_WAIT(n)  asm volatile("cp.async.wait_group %0;" :: "n"(n) : "memory")

// 256B-row swizzled tile: byte offset of half 'col' in 'row'
__device__ __forceinline__ uint32_t tl_off(int row, int col) {
    return (uint32_t)(row * 256 + ((((col >> 3) ^ (row & 7))) << 4) + (col & 7) * 2);
}

// ================================================================================
// Kernel 1: transpose + fp16-convert weights:  g_wt[mat][col][k] = W[k*384+col]
// ================================================================================
__global__ void prep_w_kernel(const float* __restrict__ kern, const float* __restrict__ rker) {
    int i = blockIdx.x * blockDim.x + threadIdx.x;
    if (i >= 2 * 384 * 128) return;
    int mat = i / (384 * 128);
    int rem = i - mat * (384 * 128);
    int col = rem >> 7;
    int k   = rem & 127;
    const float* W = mat ? rker : kern;
    g_wt[i] = __float2half_rn(W[k * 384 + col]);
}

// ================================================================================
// Kernel 2: zero the fp16 aggregation scratch (32MB)
// ================================================================================
__global__ void zero_agg_kernel() {
    const uint4 z = make_uint4(0u, 0u, 0u, 0u);
    int n16 = (B_ * N_ * D_ * 2) / 16;
    for (int i = blockIdx.x * blockDim.x + threadIdx.x; i < n16; i += gridDim.x * blockDim.x)
        reinterpret_cast<uint4*>(g_agg)[i] = z;
}

// ================================================================================
// Kernel 3: scatter-add into fp16 g_agg (2 edges/warp, v4.f16x2 REDG)
// ================================================================================
__global__ void scatter_kernel(const float* __restrict__ msgs, const int* __restrict__ conn) {
    int gwarp = (blockIdx.x * blockDim.x + threadIdx.x) >> 5;
    int lane  = threadIdx.x & 31;
    int edge  = gwarp * 2 + (lane >> 4);
    if (edge >= NEDGE) return;
    int sub = lane & 15;
    int b   = edge >> 13;
    int tgt;
    if (sub == 0) tgt = conn[edge * 2 + 1];
    tgt = __shfl_sync(0xffffffffu, tgt, lane & 16);
    const float4* mp = reinterpret_cast<const float4*>(msgs) + (size_t)edge * 32 + sub * 2;
    float4 m0 = mp[0];
    float4 m1 = mp[1];
    union { __half2 h; uint32_t u; } p0, p1, p2, p3;
    p0.h = __floats2half2_rn(m0.x, m0.y);
    p1.h = __floats2half2_rn(m0.z, m0.w);
    p2.h = __floats2half2_rn(m1.x, m1.y);
    p3.h = __floats2half2_rn(m1.z, m1.w);
    __half* dst = g_agg + ((size_t)((b << 12) + tgt)) * 128 + sub * 8;
    asm volatile("red.global.add.noftz.v4.f16x2 [%0], {%1, %2, %3, %4};"
                 :: "l"(dst), "r"(p0.u), "r"(p1.u), "r"(p2.u), "r"(p3.u) : "memory");
}

// ================================================================================
// Kernel 4: fused dual-GEMM + GRU epilogue.  2048 CTAs x 64 rows, 256 threads
// (8 warps, 2x4 grid, warp tile 32x16).  12 phases of 64 cols, cp.async 2-ring.
// 3 CTAs/SM for latency hiding.
// ================================================================================

// async copy of an N-row x 256B tile into swizzled smem (256 threads)
__device__ __forceinline__ void cp_tile(uint32_t dst, const __half* src, int nchunks, int tid) {
    const char* s = reinterpret_cast<const char*>(src);
    for (int c = tid; c < nchunks; c += 256) {
        int row = c >> 4, c16 = c & 15;
        CP_ASYNC16(dst + (uint32_t)(row * 256 + ((c16 ^ (row & 7)) << 4)), s + (size_t)c * 16);
    }
}

// phase p (0..11): gate g=p>>2, col-half hx=(p>>1)&1, sub m=p&1.
// matrix: gates z,r: m=0->Wx(mat0), m=1->Wh(mat1); gate h: m=0->Wh, m=1->Wx.
#define PH_MAT(p) (((p) < 8) ? ((p) & 1) : (1 - ((p) & 1)))
#define PH_COL(p) ((((p) >> 2) * 128) + ((((p) >> 1) & 1) * 64))
#define PH_BUF(p) (((p) & 1) ? (sb + OFF_B1) : (sb + OFF_B0))
#define PREFETCH(p) do { \
    cp_tile(PH_BUF(p), g_wt + (size_t)(PH_MAT(p) * 384 + PH_COL(p)) * 128, 1024, tid); \
    CP_COMMIT(); } while (0)

#define ZERO_ACC() do { _Pragma("unroll") \
    for (int mt = 0; mt < 2; mt++) _Pragma("unroll") \
        for (int nt = 0; nt < 2; nt++) \
            acc[mt][nt][0] = acc[mt][nt][1] = acc[mt][nt][2] = acc[mt][nt][3] = 0.f; } while (0)

// acc += A(32x128) @ B(128x16)^T  (XOR-swizzled tiles; per-lane cA, bt, r8)
#define GEMM(AROW, BROW) do { \
    _Pragma("unroll") \
    for (int kc = 0; kc < 4; kc++) { \
        uint32_t swA0 = (uint32_t)(((4*kc + cA)     ^ r8) << 4); \
        uint32_t swA1 = (uint32_t)(((4*kc + 2 + cA) ^ r8) << 4); \
        uint32_t swB  = (uint32_t)(((4*kc + bt)     ^ r8) << 4); \
        uint32_t A0[2][4], A1[2][4]; \
        _Pragma("unroll") \
        for (int mt = 0; mt < 2; mt++) { \
            ldsm4(A0[mt], (AROW) + mt * 4096 + swA0); \
            ldsm4(A1[mt], (AROW) + mt * 4096 + swA1); \
        } \
        _Pragma("unroll") \
        for (int nt = 0; nt < 2; nt++) { \
            uint32_t Bf[4]; \
            ldsm4(Bf, (BROW) + nt * 2048 + swB); \
            _Pragma("unroll") \
            for (int mt = 0; mt < 2; mt++) { \
                mma_16816(acc[mt][nt], A0[mt], Bf[0], Bf[1]); \
                mma_16816(acc[mt][nt], A1[mt], Bf[2], Bf[3]); \
            } \
        } \
    } } while (0)

#define PHASE_BEGIN_MID()  do { CP_WAIT(1); __syncthreads(); } while (0)
#define PHASE_END(p) do { __syncthreads(); if ((p) + 2 <= 11) PREFETCH((p) + 2); } while (0)

__global__ void __launch_bounds__(256, 3)
gru_gemm_kernel(const float* __restrict__ atom_state,
                const float* __restrict__ bias,
                float* __restrict__ out)
{
    extern __shared__ char smem[];
    const uint32_t sb = smem_u32(smem);
    const int tid  = threadIdx.x;
    const int wid  = tid >> 5;
    const int lane = tid & 31;
    const int wr   = wid & 1;          // row group (2 x 32 rows)
    const int wc   = wid >> 1;         // col group (4 x 16 cols)
    const int g4   = lane >> 2;
    const int tig  = lane & 3;
    const int bt   = lane >> 3;
    const int cA   = bt >> 1;
    const int r8   = lane & 7;
    const int row0 = blockIdx.x * 64;

    float* bias_s = reinterpret_cast<float*>(smem + OFF_BIAS);

    // ---- prolog: 3 cp.async groups {B(p0)}, {AG}, {B(p1)}; h LDG; bias; h STS ----
    PREFETCH(0);
    cp_tile(sb + OFF_AG, g_agg + (size_t)row0 * 128, 1024, tid);
    CP_COMMIT();
    PREFETCH(1);

    float4 hv[8];
    {
        const float4* hp = reinterpret_cast<const float4*>(atom_state + (size_t)row0 * 128);
#pragma unroll
        for (int k = 0; k < 8; k++) hv[k] = hp[tid + k * 256];
    }
    for (int i = tid; i < 768; i += 256) bias_s[i] = bias[i];
#pragma unroll
    for (int k = 0; k < 8; k++) {
        int idx = tid + k * 256;
        int row = idx >> 5, f4 = idx & 31;
        union { __half2 h2[2]; uint2 u; } cv;
        cv.h2[0] = __floats2half2_rn(hv[k].x, hv[k].y);
        cv.h2[1] = __floats2half2_rn(hv[k].z, hv[k].w);
        uint32_t off = (uint32_t)(row * 256 + (((f4 >> 1) ^ (row & 7)) << 4) + (f4 & 1) * 8);
        *reinterpret_cast<uint2*>(smem + OFF_AH + off) = cv.u;
    }

    // per-lane ldsm bases
    const int arow = wr * 32 + ((bt & 1) << 3) + r8;
    const uint32_t agRow = sb + OFF_AG + (uint32_t)arow * 256;
    const uint32_t ahRow = sb + OFF_AH + (uint32_t)arow * 256;
    const uint32_t bRow  = (uint32_t)((wc * 16 + r8) * 256);

    float acc[2][2][4];
    __half2 zpk[2][2][2][2];   // [hx][mt][nt][half]
    __half2 rpk[2][2][2][2];

    // ================= gates z (g=0) and r (g=1), col-halves =================
#pragma unroll
    for (int g = 0; g < 2; g++) {
#pragma unroll
        for (int hx = 0; hx < 2; hx++) {
            const int p0 = g * 4 + hx * 2;          // even phase: agg @ Wx
            PHASE_BEGIN_MID();
            ZERO_ACC();
            GEMM(agRow, PH_BUF(p0) + bRow);
            PHASE_END(p0);

            PHASE_BEGIN_MID();                       // odd phase: + h @ Wh
            GEMM(ahRow, PH_BUF(p0 + 1) + bRow);
            PHASE_END(p0 + 1);

            // sigma epilogue (registers + read-only bias only)
#pragma unroll
            for (int mt = 0; mt < 2; mt++)
#pragma unroll
                for (int nt = 0; nt < 2; nt++) {
                    int colb = hx * 64 + wc * 16 + nt * 8 + tig * 2;
                    float cb0 = bias_s[g * 128 + colb]     + bias_s[384 + g * 128 + colb];
                    float cb1 = bias_s[g * 128 + colb + 1] + bias_s[384 + g * 128 + colb + 1];
                    __half2 v0 = __floats2half2_rn(sigf(acc[mt][nt][0] + cb0), sigf(acc[mt][nt][1] + cb1));
                    __half2 v1 = __floats2half2_rn(sigf(acc[mt][nt][2] + cb0), sigf(acc[mt][nt][3] + cb1));
                    if (g == 0) { zpk[hx][mt][nt][0] = v0; zpk[hx][mt][nt][1] = v1; }
                    else        { rpk[hx][mt][nt][0] = v0; rpk[hx][mt][nt][1] = v1; }
                }
        }
    }

    // ================= gate h (phases 8..11) =================
#pragma unroll
    for (int hx = 0; hx < 2; hx++) {
        const int p0 = 8 + hx * 2;

        // m=0: acc = h @ Wh_h[half] ; rpk *= (acc + bh)
        PHASE_BEGIN_MID();
        ZERO_ACC();
        GEMM(ahRow, PH_BUF(p0) + bRow);
        PHASE_END(p0);
#pragma unroll
        for (int mt = 0; mt < 2; mt++)
#pragma unroll
            for (int nt = 0; nt < 2; nt++) {
                int colb = hx * 64 + wc * 16 + nt * 8 + tig * 2;
                float b0 = bias_s[384 + 256 + colb];
                float b1 = bias_s[384 + 256 + colb + 1];
                float2 rA = __half22float2(rpk[hx][mt][nt][0]);
                float2 rB = __half22float2(rpk[hx][mt][nt][1]);
                rpk[hx][mt][nt][0] = __floats2half2_rn(rA.x * (acc[mt][nt][0] + b0), rA.y * (acc[mt][nt][1] + b1));
                rpk[hx][mt][nt][1] = __floats2half2_rn(rB.x * (acc[mt][nt][2] + b0), rB.y * (acc[mt][nt][3] + b1));
            }

        // m=1: acc = agg @ Wx_h[half] ; final epilogue + store
        if (p0 + 1 < 11) { CP_WAIT(1); } else { CP_WAIT(0); }
        __syncthreads();
        ZERO_ACC();
        GEMM(agRow, PH_BUF(p0 + 1) + bRow);
        PHASE_END(p0 + 1);

#pragma unroll
        for (int mt = 0; mt < 2; mt++) {
            const int rowA = wr * 32 + mt * 16 + g4;
            const int rowB = rowA + 8;
#pragma unroll
            for (int nt = 0; nt < 2; nt++) {
                int colb = hx * 64 + wc * 16 + nt * 8 + tig * 2;
                float b0 = bias_s[256 + colb];
                float b1 = bias_s[256 + colb + 1];
                float2 tA = __half22float2(rpk[hx][mt][nt][0]);
                float2 tB = __half22float2(rpk[hx][mt][nt][1]);
                float2 zA = __half22float2(zpk[hx][mt][nt][0]);
                float2 zB = __half22float2(zpk[hx][mt][nt][1]);
                float2 hA = __half22float2(*reinterpret_cast<const __half2*>(
                    smem + OFF_AH + tl_off(rowA, colb)));
                float2 hB = __half22float2(*reinterpret_cast<const __half2*>(
                    smem + OFF_AH + tl_off(rowB, colb)));

                float hh0 = tanh_ap(acc[mt][nt][0] + b0 + tA.x);
                float hh1 = tanh_ap(acc[mt][nt][1] + b1 + tA.y);
                float hh2 = tanh_ap(acc[mt][nt][2] + b0 + tB.x);
                float hh3 = tanh_ap(acc[mt][nt][3] + b1 + tB.y);

                float2 oA = make_float2(zA.x * hA.x + (1.f - zA.x) * hh0,
                                        zA.y * hA.y + (1.f - zA.y) * hh1);
                float2 oB = make_float2(zB.x * hB.x + (1.f - zB.x) * hh2,
                                        zB.y * hB.y + (1.f - zB.y) * hh3);
                *reinterpret_cast<float2*>(out + (size_t)(row0 + rowA) * 128 + colb) = oA;
                *reinterpret_cast<float2*>(out + (size_t)(row0 + rowB) * 128 + colb) = oB;
            }
        }
    }
}

// ================================================================================
// Launch
// ================================================================================
extern "C" void kernel_launch(void* const* d_in, const int* in_sizes, int n_in,
                              void* d_out, int out_size) {
    const float* atom_state = (const float*)d_in[0];
    const float* messages   = (const float*)d_in[1];
    const int*   conn       = (const int*)d_in[2];
    const float* kern       = (const float*)d_in[3];
    const float* rker       = (const float*)d_in[4];
    const float* bias       = (const float*)d_in[5];
    float* out = (float*)d_out;

    cudaFuncSetAttribute(gru_gemm_kernel, cudaFuncAttributeMaxDynamicSharedMemorySize, SMEM_TOTAL);

    prep_w_kernel<<<(2 * 384 * 128 + 255) / 256, 256>>>(kern, rker);
    zero_agg_kernel<<<2048, 256>>>();
    scatter_kernel<<<(NEDGE / 2 * 32) / 256, 256>>>(messages, conn);
    gru_gemm_kernel<<<ROWS_TOTAL / 64, 256, SMEM_TOTAL>>>(atom_state, bias, out);
}

// round 15
// speedup vs baseline: 1.0928x; 1.0928x over previous
#include <cuda_runtime.h>
#include <cuda_fp16.h>
#include <cstdint>

// Problem constants
#define B_  32
#define N_  4096
#define E_  8192
#define D_  128
#define ROWS_TOTAL (B_*N_)        // 131072
#define NEDGE (B_*E_)             // 262144

// ---------------- device-global scratch ------------------------------------------
__device__ __half g_agg[B_*N_*D_];     // 32MB fp16 aggregation buffer
__device__ __half g_wt[2*384*128];     // transposed fp16 weights: [mat][col(384)][k(128)]

// ---------------- smem layout (bytes), 64-row CTA, 2 CTAs/SM ---------------------
// A tiles: 256B rows, XOR swizzle on 16B chunks: chunk' = chunk ^ (row&7)
// merged B stages: 256 rows x 128B (half-k), chunk' = chunk ^ (row&7) (3-bit)
#define OFF_BIAS  0                 // 768 floats (3072)
#define OFF_AG    4096              // agg  64x256B (16384)
#define OFF_AH    20480             // h    64x256B (16384)
#define OFF_B0    36864             // B ring buf 0 (32768)
#define OFF_B1    69632             // B ring buf 1 (32768)
#define SMEM_TOTAL 102400           // x2 = 204800 <= 228KB/SM

__device__ __forceinline__ uint32_t smem_u32(const void* p) {
    uint32_t a;
    asm("{ .reg .u64 t; cvta.to.shared.u64 t, %1; cvt.u32.u64 %0, t; }" : "=r"(a) : "l"(p));
    return a;
}
__device__ __forceinline__ void ldsm4(uint32_t d[4], uint32_t addr) {
    asm volatile("ldmatrix.sync.aligned.m8n8.x4.shared.b16 {%0,%1,%2,%3}, [%4];"
                 : "=r"(d[0]), "=r"(d[1]), "=r"(d[2]), "=r"(d[3]) : "r"(addr));
}
__device__ __forceinline__ void mma_16816(float c[4], const uint32_t a[4], uint32_t b0, uint32_t b1) {
    asm volatile(
        "mma.sync.aligned.m16n8k16.row.col.f32.f16.f16.f32 "
        "{%0,%1,%2,%3}, {%4,%5,%6,%7}, {%8,%9}, {%0,%1,%2,%3};"
        : "+f"(c[0]), "+f"(c[1]), "+f"(c[2]), "+f"(c[3])
        : "r"(a[0]), "r"(a[1]), "r"(a[2]), "r"(a[3]), "r"(b0), "r"(b1));
}
__device__ __forceinline__ float tanh_ap(float x) {
    float y; asm("tanh.approx.f32 %0, %1;" : "=f"(y) : "f"(x)); return y;
}
__device__ __forceinline__ float sigf(float x) { return fmaf(0.5f, tanh_ap(0.5f * x), 0.5f); }

#define CP_ASYNC16(dst, src) \
    asm volatile("cp.async.cg.shared.global [%0], [%1], 16;" :: "r"(dst), "l"(src) : "memory")
#define CP_COMMIT() asm volatile("cp.async.commit_group;" ::: "memory")
#define CP_WAIT(n)  asm volatile("cp.async.wait_group %0;" :: "n"(n) : "memory")

// 256B-row swizzled tile: byte offset of half 'col' in 'row'
__device__ __forceinline__ uint32_t tl_off(int row, int col) {
    return (uint32_t)(row * 256 + ((((col >> 3) ^ (row & 7))) << 4) + (col & 7) * 2);
}

// ================================================================================
// Kernel 1: transpose + fp16-convert weights:  g_wt[mat][col][k] = W[k*384+col]
// ================================================================================
__global__ void prep_w_kernel(const float* __restrict__ kern, const float* __restrict__ rker) {
    int i = blockIdx.x * blockDim.x + threadIdx.x;
    if (i >= 2 * 384 * 128) return;
    int mat = i / (384 * 128);
    int rem = i - mat * (384 * 128);
    int col = rem >> 7;
    int k   = rem & 127;
    const float* W = mat ? rker : kern;
    g_wt[i] = __float2half_rn(W[k * 384 + col]);
}

// ================================================================================
// Kernel 2: zero the fp16 aggregation scratch (32MB)
// ================================================================================
__global__ void zero_agg_kernel() {
    const uint4 z = make_uint4(0u, 0u, 0u, 0u);
    int n16 = (B_ * N_ * D_ * 2) / 16;
    for (int i = blockIdx.x * blockDim.x + threadIdx.x; i < n16; i += gridDim.x * blockDim.x)
        reinterpret_cast<uint4*>(g_agg)[i] = z;
}

// ================================================================================
// Kernel 3: scatter-add into fp16 g_agg (2 edges/warp, v4.f16x2 REDG)
// ================================================================================
__global__ void scatter_kernel(const float* __restrict__ msgs, const int* __restrict__ conn) {
    int gwarp = (blockIdx.x * blockDim.x + threadIdx.x) >> 5;
    int lane  = threadIdx.x & 31;
    int edge  = gwarp * 2 + (lane >> 4);
    if (edge >= NEDGE) return;
    int sub = lane & 15;
    int b   = edge >> 13;
    int tgt;
    if (sub == 0) tgt = conn[edge * 2 + 1];
    tgt = __shfl_sync(0xffffffffu, tgt, lane & 16);
    const float4* mp = reinterpret_cast<const float4*>(msgs) + (size_t)edge * 32 + sub * 2;
    float4 m0 = mp[0];
    float4 m1 = mp[1];
    union { __half2 h; uint32_t u; } p0, p1, p2, p3;
    p0.h = __floats2half2_rn(m0.x, m0.y);
    p1.h = __floats2half2_rn(m0.z, m0.w);
    p2.h = __floats2half2_rn(m1.x, m1.y);
    p3.h = __floats2half2_rn(m1.z, m1.w);
    __half* dst = g_agg + ((size_t)((b << 12) + tgt)) * 128 + sub * 8;
    asm volatile("red.global.add.noftz.v4.f16x2 [%0], {%1, %2, %3, %4};"
                 :: "l"(dst), "r"(p0.u), "r"(p1.u), "r"(p2.u), "r"(p3.u) : "memory");
}

// ================================================================================
// Kernel 4: fused dual-GEMM + GRU epilogue.
// 2048 CTAs x 64 rows, 256 threads (8 warps, 2x4 grid).
// Merged z|r phases: warp tile 32x64 (z-strip + r-strip interleaved per warp).
// 6 cp.async B stages (32KB each), 2-buffer ring.
// ================================================================================

// full-k B tile: 128 rows x 256B (16 chunks/row)
__device__ __forceinline__ void pref_full(uint32_t dst, const __half* src, int tid) {
    const char* s = reinterpret_cast<const char*>(src);
    for (int c = tid; c < 2048; c += 256) {
        int row = c >> 4, c16 = c & 15;
        CP_ASYNC16(dst + (uint32_t)(row * 256 + ((c16 ^ (row & 7)) << 4)), s + (size_t)c * 16);
    }
    CP_COMMIT();
}
// half-k merged B tile: 256 rows x 128B (8 chunks/row); src rows are 256B, k-half kh
__device__ __forceinline__ void pref_half(uint32_t dst, const __half* srcbase, int kh, int tid) {
    const char* s = reinterpret_cast<const char*>(srcbase) + kh * 128;
    for (int c = tid; c < 2048; c += 256) {
        int row = c >> 3, c8 = c & 7;
        CP_ASYNC16(dst + (uint32_t)(row * 128 + ((c8 ^ (row & 7)) << 4)),
                   s + (size_t)row * 256 + c8 * 16);
    }
    CP_COMMIT();
}
// A tile (agg): 64 rows x 256B
__device__ __forceinline__ void pref_ag(uint32_t dst, const __half* src, int tid) {
    const char* s = reinterpret_cast<const char*>(src);
    for (int c = tid; c < 1024; c += 256) {
        int row = c >> 4, c16 = c & 15;
        CP_ASYNC16(dst + (uint32_t)(row * 256 + ((c16 ^ (row & 7)) << 4)), s + (size_t)c * 16);
    }
    CP_COMMIT();
}

// merged half-k GEMM: acc[2][8] += A(32 x k64) @ B strips; S = k-half
#define GEMM_M(S, AROW, BZ, BR) do { \
    _Pragma("unroll") \
    for (int kcp = 0; kcp < 2; kcp++) { \
        int gkc = (S) * 2 + kcp; \
        uint32_t swA0 = (uint32_t)(((4*gkc + cA)     ^ r8) << 4); \
        uint32_t swA1 = (uint32_t)(((4*gkc + 2 + cA) ^ r8) << 4); \
        uint32_t swB  = (uint32_t)(((4*kcp + bt)     ^ r8) << 4); \
        uint32_t A0[2][4], A1[2][4]; \
        _Pragma("unroll") \
        for (int mt = 0; mt < 2; mt++) { \
            ldsm4(A0[mt], (AROW) + mt * 4096 + swA0); \
            ldsm4(A1[mt], (AROW) + mt * 4096 + swA1); \
        } \
        _Pragma("unroll") \
        for (int nt = 0; nt < 8; nt++) { \
            uint32_t baddr = ((nt < 4) ? ((BZ) + nt * 1024) : ((BR) + (nt - 4) * 1024)) + swB; \
            uint32_t Bf[4]; \
            ldsm4(Bf, baddr); \
            _Pragma("unroll") \
            for (int mt = 0; mt < 2; mt++) { \
                mma_16816(acc[mt][nt], A0[mt], Bf[0], Bf[1]); \
                mma_16816(acc[mt][nt], A1[mt], Bf[2], Bf[3]); \
            } \
        } \
    } } while (0)

// single-gate full-k GEMM: acc[2][0..3] += A(32x128) @ B(128x32)^T
#define GEMM_S(AROW, BBASE) do { \
    _Pragma("unroll") \
    for (int kc = 0; kc < 4; kc++) { \
        uint32_t swA0 = (uint32_t)(((4*kc + cA)     ^ r8) << 4); \
        uint32_t swA1 = (uint32_t)(((4*kc + 2 + cA) ^ r8) << 4); \
        uint32_t swB  = (uint32_t)(((4*kc + bt)     ^ r8) << 4); \
        uint32_t A0[2][4], A1[2][4]; \
        _Pragma("unroll") \
        for (int mt = 0; mt < 2; mt++) { \
            ldsm4(A0[mt], (AROW) + mt * 4096 + swA0); \
            ldsm4(A1[mt], (AROW) + mt * 4096 + swA1); \
        } \
        _Pragma("unroll") \
        for (int nt = 0; nt < 4; nt++) { \
            uint32_t Bf[4]; \
            ldsm4(Bf, (BBASE) + nt * 2048 + swB); \
            _Pragma("unroll") \
            for (int mt = 0; mt < 2; mt++) { \
                mma_16816(acc[mt][nt], A0[mt], Bf[0], Bf[1]); \
                mma_16816(acc[mt][nt], A1[mt], Bf[2], Bf[3]); \
            } \
        } \
    } } while (0)

__global__ void __launch_bounds__(256, 2)
gru_gemm_kernel(const float* __restrict__ atom_state,
                const float* __restrict__ bias,
                float* __restrict__ out)
{
    extern __shared__ char smem[];
    const uint32_t sb = smem_u32(smem);
    const int tid  = threadIdx.x;
    const int wid  = tid >> 5;
    const int lane = tid & 31;
    const int wr   = wid & 1;          // row group (2 x 32 rows)
    const int wc   = wid >> 1;         // col group (4 x 32 cols per gate)
    const int g4   = lane >> 2;
    const int tig  = lane & 3;
    const int bt   = lane >> 3;
    const int cA   = bt >> 1;
    const int r8   = lane & 7;
    const int row0 = blockIdx.x * 64;

    float* bias_s = reinterpret_cast<float*>(smem + OFF_BIAS);

    // ---- prolog: {B s0: Wx_zr k0}, {AG}, {B s1: Wx_zr k1}; bias; h staged now ----
    pref_half(sb + OFF_B0, g_wt, 0, tid);
    pref_ag(sb + OFF_AG, g_agg + (size_t)row0 * 128, tid);
    pref_half(sb + OFF_B1, g_wt, 1, tid);

    {
        const float4* hp = reinterpret_cast<const float4*>(atom_state + (size_t)row0 * 128);
        float4 hv[8];
#pragma unroll
        for (int k = 0; k < 8; k++) hv[k] = hp[tid + k * 256];
        for (int i = tid; i < 768; i += 256) bias_s[i] = bias[i];
#pragma unroll
        for (int k = 0; k < 8; k++) {
            int idx = tid + k * 256;
            int row = idx >> 5, f4 = idx & 31;
            union { __half2 h2[2]; uint2 u; } cv;
            cv.h2[0] = __floats2half2_rn(hv[k].x, hv[k].y);
            cv.h2[1] = __floats2half2_rn(hv[k].z, hv[k].w);
            uint32_t off = (uint32_t)(row * 256 + (((f4 >> 1) ^ (row & 7)) << 4) + (f4 & 1) * 8);
            *reinterpret_cast<uint2*>(smem + OFF_AH + off) = cv.u;
        }
    }

    // per-lane ldsm bases
    const int arow = wr * 32 + ((bt & 1) << 3) + r8;
    const uint32_t agRow = sb + OFF_AG + (uint32_t)arow * 256;
    const uint32_t ahRow = sb + OFF_AH + (uint32_t)arow * 256;
    // merged-stage B strip bases (128B rows): z strip rows wc*32+, r strip rows 128+wc*32+
    const uint32_t bz0 = sb + OFF_B0 + (uint32_t)((wc * 32 + r8) * 128);
    const uint32_t br0 = bz0 + 16384;
    const uint32_t bz1 = sb + OFF_B1 + (uint32_t)((wc * 32 + r8) * 128);
    const uint32_t br1 = bz1 + 16384;
    // single-stage B base (256B rows)
    const uint32_t bs0 = sb + OFF_B0 + (uint32_t)((wc * 32 + r8) * 256);
    const uint32_t bs1 = sb + OFF_B1 + (uint32_t)((wc * 32 + r8) * 256);

    float acc[2][8][4];
    __half2 zpk[2][4][2];
    __half2 rpk[2][4][2];

#pragma unroll
    for (int mt = 0; mt < 2; mt++)
#pragma unroll
        for (int nt = 0; nt < 8; nt++)
            acc[mt][nt][0] = acc[mt][nt][1] = acc[mt][nt][2] = acc[mt][nt][3] = 0.f;

    // ===== stage 0: agg @ Wx_zr (k0) =====
    CP_WAIT(1);                       // B0 + AG done (B1 pending); AH via sync
    __syncthreads();
    GEMM_M(0, agRow, bz0, br0);
    __syncthreads();
    pref_half(sb + OFF_B0, g_wt + 384 * 128, 0, tid);   // Wh_zr k0

    // ===== stage 1: agg @ Wx_zr (k1) =====
    CP_WAIT(1);
    __syncthreads();
    GEMM_M(1, agRow, bz1, br1);
    __syncthreads();
    pref_half(sb + OFF_B1, g_wt + 384 * 128, 1, tid);   // Wh_zr k1

    // ===== stage 2: + h @ Wh_zr (k0) =====
    CP_WAIT(1);
    __syncthreads();
    GEMM_M(0, ahRow, bz0, br0);
    __syncthreads();
    pref_full(sb + OFF_B0, g_wt + (size_t)(384 + 256) * 128, tid);   // Wh_h

    // ===== stage 3: + h @ Wh_zr (k1) =====
    CP_WAIT(1);
    __syncthreads();
    GEMM_M(1, ahRow, bz1, br1);
    __syncthreads();
    pref_full(sb + OFF_B1, g_wt + (size_t)256 * 128, tid);           // Wx_h

    // ===== sigma epilogue: z (nt 0..3) and r (nt 4..7), warp's own 32 cols =====
#pragma unroll
    for (int mt = 0; mt < 2; mt++)
#pragma unroll
        for (int nt = 0; nt < 4; nt++) {
            int col = wc * 32 + nt * 8 + tig * 2;
            float zb0 = bias_s[col]     + bias_s[384 + col];
            float zb1 = bias_s[col + 1] + bias_s[384 + col + 1];
            zpk[mt][nt][0] = __floats2half2_rn(sigf(acc[mt][nt][0] + zb0), sigf(acc[mt][nt][1] + zb1));
            zpk[mt][nt][1] = __floats2half2_rn(sigf(acc[mt][nt][2] + zb0), sigf(acc[mt][nt][3] + zb1));
            float rb0 = bias_s[128 + col]     + bias_s[384 + 128 + col];
            float rb1 = bias_s[128 + col + 1] + bias_s[384 + 128 + col + 1];
            rpk[mt][nt][0] = __floats2half2_rn(sigf(acc[mt][nt + 4][0] + rb0), sigf(acc[mt][nt + 4][1] + rb1));
            rpk[mt][nt][1] = __floats2half2_rn(sigf(acc[mt][nt + 4][2] + rb0), sigf(acc[mt][nt + 4][3] + rb1));
        }

    // ===== stage 4: acc = h @ Wh_h ; rpk *= (acc + bh) =====
    CP_WAIT(1);
    __syncthreads();
#pragma unroll
    for (int mt = 0; mt < 2; mt++)
#pragma unroll
        for (int nt = 0; nt < 4; nt++)
            acc[mt][nt][0] = acc[mt][nt][1] = acc[mt][nt][2] = acc[mt][nt][3] = 0.f;
    GEMM_S(ahRow, bs0);
#pragma unroll
    for (int mt = 0; mt < 2; mt++)
#pragma unroll
        for (int nt = 0; nt < 4; nt++) {
            int col = wc * 32 + nt * 8 + tig * 2;
            float b0 = bias_s[384 + 256 + col];
            float b1 = bias_s[384 + 256 + col + 1];
            float2 rA = __half22float2(rpk[mt][nt][0]);
            float2 rB = __half22float2(rpk[mt][nt][1]);
            rpk[mt][nt][0] = __floats2half2_rn(rA.x * (acc[mt][nt][0] + b0), rA.y * (acc[mt][nt][1] + b1));
            rpk[mt][nt][1] = __floats2half2_rn(rB.x * (acc[mt][nt][2] + b0), rB.y * (acc[mt][nt][3] + b1));
        }

    // ===== stage 5: acc = agg @ Wx_h ; final epilogue =====
    CP_WAIT(0);
    __syncthreads();
#pragma unroll
    for (int mt = 0; mt < 2; mt++)
#pragma unroll
        for (int nt = 0; nt < 4; nt++)
            acc[mt][nt][0] = acc[mt][nt][1] = acc[mt][nt][2] = acc[mt][nt][3] = 0.f;
    GEMM_S(agRow, bs1);

#pragma unroll
    for (int mt = 0; mt < 2; mt++) {
        const int rowA = wr * 32 + mt * 16 + g4;
        const int rowB = rowA + 8;
#pragma unroll
        for (int nt = 0; nt < 4; nt++) {
            int col = wc * 32 + nt * 8 + tig * 2;
            float b0 = bias_s[256 + col];
            float b1 = bias_s[256 + col + 1];
            float2 tA = __half22float2(rpk[mt][nt][0]);
            float2 tB = __half22float2(rpk[mt][nt][1]);
            float2 zA = __half22float2(zpk[mt][nt][0]);
            float2 zB = __half22float2(zpk[mt][nt][1]);
            float2 hA = __half22float2(*reinterpret_cast<const __half2*>(
                smem + OFF_AH + tl_off(rowA, col)));
            float2 hB = __half22float2(*reinterpret_cast<const __half2*>(
                smem + OFF_AH + tl_off(rowB, col)));

            float hh0 = tanh_ap(acc[mt][nt][0] + b0 + tA.x);
            float hh1 = tanh_ap(acc[mt][nt][1] + b1 + tA.y);
            float hh2 = tanh_ap(acc[mt][nt][2] + b0 + tB.x);
            float hh3 = tanh_ap(acc[mt][nt][3] + b1 + tB.y);

            float2 oA = make_float2(zA.x * hA.x + (1.f - zA.x) * hh0,
                                    zA.y * hA.y + (1.f - zA.y) * hh1);
            float2 oB = make_float2(zB.x * hB.x + (1.f - zB.x) * hh2,
                                    zB.y * hB.y + (1.f - zB.y) * hh3);
            *reinterpret_cast<float2*>(out + (size_t)(row0 + rowA) * 128 + col) = oA;
            *reinterpret_cast<float2*>(out + (size_t)(row0 + rowB) * 128 + col) = oB;
        }
    }
}

// ================================================================================
// Launch
// ================================================================================
extern "C" void kernel_launch(void* const* d_in, const int* in_sizes, int n_in,
                              void* d_out, int out_size) {
    const float* atom_state = (const float*)d_in[0];
    const float* messages   = (const float*)d_in[1];
    const int*   conn       = (const int*)d_in[2];
    const float* kern       = (const float*)d_in[3];
    const float* rker       = (const float*)d_in[4];
    const float* bias       = (const float*)d_in[5];
    float* out = (float*)d_out;

    cudaFuncSetAttribute(gru_gemm_kernel, cudaFuncAttributeMaxDynamicSharedMemorySize, SMEM_TOTAL);

    prep_w_kernel<<<(2 * 384 * 128 + 255) / 256, 256>>>(kern, rker);
    zero_agg_kernel<<<2048, 256>>>();
    scatter_kernel<<<(NEDGE / 2 * 32) / 256, 256>>>(messages, conn);
    gru_gemm_kernel<<<ROWS_TOTAL / 64, 256, SMEM_TOTAL>>>(atom_state, bias, out);
}